// round 16
// baseline (speedup 1.0000x reference)
#include <cuda_runtime.h>
#include <cuda_fp16.h>
#include <cstdint>

// ---------------- problem constants ----------------
static constexpr int TOKENS = 4096;
static constexpr int IN_F   = 4096;
static constexpr int OUT_F  = 11008;

static constexpr int BM = 128;
static constexpr int BN = 128;
static constexpr int BK = 64;          // 64 fp16 = 128 bytes per row (SW128 atom row)
static constexpr int STAGES = 3;

static constexpr int M_TILES = TOKENS / BM;   // 32
static constexpr int N_TILES = OUT_F / BN;    // 86
static constexpr int K_TILES = IN_F / BK;     // 64
static constexpr int N_TILES_TOTAL = M_TILES * N_TILES; // 2752

static constexpr int TILE_BYTES = 128 * BK * 2;     // 16384 (A tile == B tile)
static constexpr int STAGE_BYTES = 2 * TILE_BYTES;  // 32768
static constexpr int SMEM_BYTES = STAGES * STAGE_BYTES + 16; // 98320

static constexpr int X_BLOCKS = M_TILES * K_TILES;  // 2048
static constexpr int W_BLOCKS = N_TILES * K_TILES;  // 5504
static constexpr int PREP_UNITS = X_BLOCKS + W_BLOCKS; // 7552

static constexpr int GRID_GEMM = 296;  // 148 SMs x 2 CTAs, exactly resident
static constexpr int PREP_CTAS = 96;   // producer CTAs (join GEMM when prep done)

// ---------------- device scratch (no cudaMalloc allowed) ----------------
__device__ __align__(1024) uint8_t g_xbuf[(size_t)M_TILES * K_TILES * TILE_BYTES]; // 32 MB
__device__ __align__(1024) uint8_t g_wbuf[(size_t)N_TILES * K_TILES * TILE_BYTES]; // 88 MB
__device__ int g_prep_ctr;
__device__ int g_tile_ctr;
__device__ int g_exit_ctr;
__device__ int g_x_row_done[M_TILES];   // counts to 64
__device__ int g_w_row_done[N_TILES];   // counts to 64

// ---------------- helpers ----------------
__device__ __forceinline__ uint32_t smem_u32(const void* p) {
    uint32_t a;
    asm("{ .reg .u64 t; cvta.to.shared.u64 t, %1; cvt.u32.u64 %0, t; }" : "=r"(a) : "l"(p));
    return a;
}
__device__ __forceinline__ uint32_t h2u(__half2 h) { uint32_t u; __builtin_memcpy(&u, &h, 4); return u; }
__device__ __forceinline__ uint32_t swz(uint32_t off) { return off ^ ((off >> 3) & 0x70); }

__device__ __forceinline__ void cpasync16(uint32_t dst, const void* src) {
    asm volatile("cp.async.cg.shared.global [%0], [%1], 16;" :: "r"(dst), "l"(src));
}
__device__ __forceinline__ void cp_commit() { asm volatile("cp.async.commit_group;" ::: "memory"); }
__device__ __forceinline__ void cp_wait1()  { asm volatile("cp.async.wait_group 1;" ::: "memory"); }
__device__ __forceinline__ void cp_wait0()  { asm volatile("cp.async.wait_group 0;" ::: "memory"); }

__device__ __forceinline__ void ldsm4(uint32_t* r, uint32_t addr) {
    asm volatile("ldmatrix.sync.aligned.m8n8.x4.shared.b16 {%0,%1,%2,%3}, [%4];"
                 : "=r"(r[0]), "=r"(r[1]), "=r"(r[2]), "=r"(r[3]) : "r"(addr) : "memory");
}
__device__ __forceinline__ void mma16816(float* c, const uint32_t* a, const uint32_t* b) {
    asm volatile(
        "mma.sync.aligned.m16n8k16.row.col.f32.f16.f16.f32 "
        "{%0,%1,%2,%3}, {%4,%5,%6,%7}, {%8,%9}, {%0,%1,%2,%3};"
        : "+f"(c[0]), "+f"(c[1]), "+f"(c[2]), "+f"(c[3])
        : "r"(a[0]), "r"(a[1]), "r"(a[2]), "r"(a[3]), "r"(b[0]), "r"(b[1]));
}

// ---------------- fused persistent kernel ----------------
__global__ void __launch_bounds__(256, 2) fused_kernel(const float* __restrict__ x,
                                                       const int* __restrict__ wp,
                                                       const float* __restrict__ scale,
                                                       const float* __restrict__ zero,
                                                       float* __restrict__ out) {
    extern __shared__ __align__(1024) uint8_t sm[];
    uint32_t sb = smem_u32(sm);
    volatile int* s_slot = (volatile int*)(sm + STAGES * STAGE_BYTES);
    const int tid  = threadIdx.x;
    const int lane = tid & 31;
    const int warp = tid >> 5;

    // ================= producer phase (CTAs 0..PREP_CTAS-1) =================
    if (blockIdx.x < PREP_CTAS) {
        const int r = tid >> 1;      // row 0..127 within tile
        const int h = tid & 1;       // half of the 128B row
        while (true) {
            if (tid == 0) s_slot[0] = atomicAdd(&g_prep_ctr, 1);
            __syncthreads();
            const int u = s_slot[0];
            __syncthreads();
            if (u >= PREP_UNITS) break;
            if (u < X_BLOCKS) {
                // x fp32 -> fp16, tiled + SW128
                const int mt = u / K_TILES;
                const int kt = u % K_TILES;
                const float4* src = (const float4*)(x + (size_t)(mt * BM + r) * IN_F + kt * BK + h * 32);
                uint8_t* dst = g_xbuf + (size_t)u * TILE_BYTES;
#pragma unroll
                for (int g = 0; g < 4; g++) {
                    float4 a = src[2 * g];
                    float4 b = src[2 * g + 1];
                    uint4 v;
                    v.x = h2u(__floats2half2_rn(a.x, a.y));
                    v.y = h2u(__floats2half2_rn(a.z, a.w));
                    v.z = h2u(__floats2half2_rn(b.x, b.y));
                    v.w = h2u(__floats2half2_rn(b.z, b.w));
                    uint32_t off = (uint32_t)(r * 128 + (h * 4 + g) * 16);
                    *(uint4*)(dst + swz(off)) = v;
                }
            } else {
                // packed nibbles (int32 per byte) -> fp16 dequant W, tiled + SW128
                const int wu = u - X_BLOCKS;
                const int nt = wu / K_TILES;
                const int kt = wu % K_TILES;
                const int row = nt * BN + r;
                const float s = scale[row];
                const float b = -zero[row] * s;
                const uint4* src = (const uint4*)(wp + (size_t)row * (IN_F / 2) + kt * (BK / 2) + h * 16);
                uint8_t* dst = g_wbuf + (size_t)wu * TILE_BYTES;
#pragma unroll
                for (int jj = 0; jj < 4; jj++) {
                    uint4 q = src[jj];
                    uint32_t e[4] = {q.x, q.y, q.z, q.w};
                    uint32_t hh[4];
#pragma unroll
                    for (int t = 0; t < 4; t++) {
                        float v0 = fmaf((float)(e[t] & 15u), s, b);          // even k
                        float v1 = fmaf((float)((e[t] >> 4) & 15u), s, b);   // odd k
                        hh[t] = h2u(__floats2half2_rn(v0, v1));
                    }
                    uint4 v = make_uint4(hh[0], hh[1], hh[2], hh[3]);
                    uint32_t off = (uint32_t)(r * 128 + (h * 4 + jj) * 16);
                    *(uint4*)(dst + swz(off)) = v;
                }
            }
            __threadfence();          // make this unit's stores visible (release half)
            __syncthreads();
            if (tid == 0) {
                if (u < X_BLOCKS) atomicAdd(&g_x_row_done[u / K_TILES], 1);
                else              atomicAdd(&g_w_row_done[(u - X_BLOCKS) / K_TILES], 1);
            }
        }
    }

    // ================= GEMM phase (all CTAs) =================
    const int warp_m = warp & 3;
    const int warp_n = warp >> 2;
    const uint32_t cp_off = (uint32_t)tid * 64;

    const int a_row = warp_m * 32 + (lane & 15);
    const uint32_t a_xor = (uint32_t)((a_row & 7) << 4);
    const uint32_t a_cb  = (uint32_t)((lane >> 4) << 4);
    const int b_row = warp_n * 64 + (lane & 7) + ((lane >> 4) << 3);
    const uint32_t b_xor = (uint32_t)((b_row & 7) << 4);
    const uint32_t b_cb  = (uint32_t)((lane & 8) << 1);

    const uint32_t aoff0 = (uint32_t)(a_row +  0) * 128;
    const uint32_t aoff1 = (uint32_t)(a_row + 16) * 128;
    uint32_t boff[4];
#pragma unroll
    for (int p = 0; p < 4; p++) boff[p] = (uint32_t)(b_row + 16 * p) * 128;

    uint32_t bfr[2][16];
    uint32_t afr[2][4];

    while (true) {
        if (tid == 0) s_slot[0] = atomicAdd(&g_tile_ctr, 1);
        __syncthreads();
        const int tile = s_slot[0];
        if (tile >= N_TILES_TOTAL) break;
        const int mt = tile % M_TILES;
        const int nt = tile / M_TILES;

        // wait until the needed x-row and W-row tiles are fully produced
        if (tid == 0) {
            volatile int* xr = &g_x_row_done[mt];
            volatile int* wr = &g_w_row_done[nt];
            while (*xr < K_TILES || *wr < K_TILES) __nanosleep(200);
            __threadfence();   // acquire half
        }
        __syncthreads();

        const uint8_t* ag = g_xbuf + (size_t)(mt * K_TILES) * TILE_BYTES;
        const uint8_t* bg = g_wbuf + (size_t)(nt * K_TILES) * TILE_BYTES;

        cp_wait0();   // drain stale groups before rewriting stages

        // prologue: stages 0 and 1
#pragma unroll
        for (int s = 0; s < 2; s++) {
            uint32_t dA = sb + s * STAGE_BYTES + cp_off;
            uint32_t dB = dA + TILE_BYTES;
            const uint8_t* srcA = ag + (size_t)s * TILE_BYTES + cp_off;
            const uint8_t* srcB = bg + (size_t)s * TILE_BYTES + cp_off;
#pragma unroll
            for (int j = 0; j < 4; j++) {
                cpasync16(dA + j * 16, srcA + j * 16);
                cpasync16(dB + j * 16, srcB + j * 16);
            }
            cp_commit();
        }

        float acc[2][8][4];
#pragma unroll
        for (int i = 0; i < 2; i++)
#pragma unroll
            for (int j = 0; j < 8; j++)
#pragma unroll
                for (int q = 0; q < 4; q++) acc[i][j][q] = 0.f;

#pragma unroll 1
        for (int kt = 0; kt < K_TILES; kt++) {
            cp_wait1();
            __syncthreads();

            if (kt + 2 < K_TILES) {
                int s = (kt + 2) % STAGES;
                uint32_t dA = sb + s * STAGE_BYTES + cp_off;
                uint32_t dB = dA + TILE_BYTES;
                const uint8_t* srcA = ag + (size_t)(kt + 2) * TILE_BYTES + cp_off;
                const uint8_t* srcB = bg + (size_t)(kt + 2) * TILE_BYTES + cp_off;
#pragma unroll
                for (int j = 0; j < 4; j++) {
                    cpasync16(dA + j * 16, srcA + j * 16);
                    cpasync16(dB + j * 16, srcB + j * 16);
                }
            }
            cp_commit();

            uint32_t sA = sb + (kt % STAGES) * STAGE_BYTES;
            uint32_t sB = sA + TILE_BYTES;

            // prime B for k16=0
            {
                uint32_t kx = b_cb ^ b_xor;
#pragma unroll
                for (int p = 0; p < 4; p++) ldsm4(&bfr[0][4 * p], sB + boff[p] + kx);
            }

#pragma unroll
            for (int k16 = 0; k16 < 4; k16++) {
                uint32_t ka = ((uint32_t)(k16 * 32) + a_cb) ^ a_xor;
                ldsm4(afr[0], sA + aoff0 + ka);
                ldsm4(afr[1], sA + aoff1 + ka);
                if (k16 < 3) {
                    uint32_t kx = ((uint32_t)((k16 + 1) * 32) + b_cb) ^ b_xor;
#pragma unroll
                    for (int p = 0; p < 4; p++) ldsm4(&bfr[(k16 + 1) & 1][4 * p], sB + boff[p] + kx);
                }
#pragma unroll
                for (int p = 0; p < 4; p++) {
                    const uint32_t* bb = &bfr[k16 & 1][4 * p];
                    mma16816(acc[0][2 * p + 0], afr[0], bb + 0);
                    mma16816(acc[0][2 * p + 1], afr[0], bb + 2);
                    mma16816(acc[1][2 * p + 0], afr[1], bb + 0);
                    mma16816(acc[1][2 * p + 1], afr[1], bb + 2);
                }
            }
        }

        // epilogue
        const int m_lo = mt * BM + warp_m * 32 + (lane >> 2);
        const int n_lo = nt * BN + warp_n * 64 + 2 * (lane & 3);
#pragma unroll
        for (int mtile = 0; mtile < 2; mtile++) {
            int m0 = m_lo + 16 * mtile;
            float* o0 = out + (size_t)m0 * OUT_F + n_lo;
            float* o1 = o0 + (size_t)8 * OUT_F;
#pragma unroll
            for (int p = 0; p < 8; p++) {
                float2 v0, v1;
                v0.x = acc[mtile][p][0];
                v0.y = acc[mtile][p][1];
                v1.x = acc[mtile][p][2];
                v1.y = acc[mtile][p][3];
                *(float2*)(o0 + 8 * p) = v0;
                *(float2*)(o1 + 8 * p) = v1;
            }
        }
    }

    // ================= exit: last CTA resets state for the next replay =================
    __syncthreads();
    if (tid == 0) {
        __threadfence();
        int prev = atomicAdd(&g_exit_ctr, 1);
        if (prev == GRID_GEMM - 1) {
            g_prep_ctr = 0;
            g_tile_ctr = 0;
            for (int i = 0; i < M_TILES; i++) g_x_row_done[i] = 0;
            for (int i = 0; i < N_TILES; i++) g_w_row_done[i] = 0;
            __threadfence();
            g_exit_ctr = 0;
            __threadfence();
        }
    }
}

// ---------------- launch ----------------
extern "C" void kernel_launch(void* const* d_in, const int* in_sizes, int n_in,
                              void* d_out, int out_size) {
    const float* x     = (const float*)d_in[0];
    const int*   wpack = (const int*)d_in[1];   // uint8 promoted to int32 by harness
    const float* scale = (const float*)d_in[2];
    const float* zero  = (const float*)d_in[3];
    float*       out   = (float*)d_out;

    cudaFuncSetAttribute(fused_kernel, cudaFuncAttributeMaxDynamicSharedMemorySize, SMEM_BYTES);

    fused_kernel<<<GRID_GEMM, 256, SMEM_BYTES>>>(x, wpack, scale, zero, out);
}